// round 12
// baseline (speedup 1.0000x reference)
#include <cuda_runtime.h>
#include <cstdint>

#define NB    128
#define NPRI  32768
#define TOPK  400
#define KEEPK 200
#define WORDS 13
#define CONF_T 0.5f
#define NMS_T  0.5f
#define BIGNEG -1000000000.0f
#define HBINS 512
#define HBASE 12224u          // order_f(0.5) >> 18
#define SEGS  16
#define SEGBOX (NPRI / SEGS)

__device__ unsigned           g_score[NB * NPRI];
__device__ unsigned long long g_cand[NB * NPRI];   // candidate keys per image
__device__ unsigned           g_hist[NB * HBINS];
__device__ unsigned           g_thr[NB];
__device__ int                g_ccnt[NB];
__device__ float4             g_box4[NB * TOPK];   // x1,y1,x2,y2
__device__ float4             g_aux[NB * TOPK];    // area, score, label, 0
__device__ unsigned           g_sup[NB * TOPK * WORDS];

__device__ __forceinline__ unsigned order_f(float f) {
    unsigned u = __float_as_uint(f);
    return (u & 0x80000000u) ? ~u : (u | 0x80000000u);
}
__device__ __forceinline__ float unorder_f(unsigned u) {
    unsigned v = (u & 0x80000000u) ? (u ^ 0x80000000u) : ~u;
    return __uint_as_float(v);
}

// ============ K1: stream pred, emit ordered scores + 512-bin histogram ======
__global__ __launch_bounds__(256)
void k1_score(const float* __restrict__ pred) {
    const int b   = blockIdx.x >> 4;
    const int seg = blockIdx.x & 15;
    __shared__ unsigned sh[HBINS];
    sh[threadIdx.x] = 0; sh[threadIdx.x + 256] = 0;
    __syncthreads();

    const float4* P4 = reinterpret_cast<const float4*>(
        pred + (size_t)b * NPRI * 6 + (size_t)seg * SEGBOX * 6);
    uint2* S2 = reinterpret_cast<uint2*>(g_score + (size_t)b * NPRI + seg * SEGBOX);

    #pragma unroll
    for (int it = 0; it < 4; it++) {
        int e = it * 256 + threadIdx.x;
        float4 a1 = P4[3 * e + 1];
        float4 a2 = P4[3 * e + 2];
        float s0 = fmaxf(a1.x, a1.y);
        float s1 = fmaxf(a2.z, a2.w);
        unsigned u0 = order_f((s0 > CONF_T) ? s0 : BIGNEG);
        unsigned u1 = order_f((s1 > CONF_T) ? s1 : BIGNEG);
        S2[e] = make_uint2(u0, u1);
        if (s0 > CONF_T) atomicAdd(&sh[min(511u, (u0 >> 18) - HBASE)], 1u);
        if (s1 > CONF_T) atomicAdd(&sh[min(511u, (u1 >> 18) - HBASE)], 1u);
    }
    __syncthreads();
    #pragma unroll
    for (int i = threadIdx.x; i < HBINS; i += 256) {
        unsigned v = sh[i];
        if (v) atomicAdd(&g_hist[b * HBINS + i], v);
    }
}

// ============ K2t: per-image threshold from histogram =======================
__global__ __launch_bounds__(512)
void k2t_thresh() {
    const int b = blockIdx.x;
    const int tid = threadIdx.x;
    __shared__ unsigned s_ss[HBINS];
    __shared__ int s_v;
    s_ss[tid] = g_hist[b * HBINS + tid];
    g_hist[b * HBINS + tid] = 0;            // reset for next replay
    if (tid == 0) { s_v = 0; g_ccnt[b] = 0; }
    __syncthreads();
    for (int d = 1; d < HBINS; d <<= 1) {
        unsigned v = (tid + d < HBINS) ? s_ss[tid + d] : 0u;
        __syncthreads();
        s_ss[tid] += v;
        __syncthreads();
    }
    {
        bool hit = (s_ss[tid] >= TOPK) && (tid == HBINS - 1 || s_ss[tid + 1] < TOPK);
        if (hit) s_v = tid;
    }
    __syncthreads();
    if (tid == 0) g_thr[b] = (HBASE + (unsigned)s_v) << 18;
}

// ============ K2g: wide gather of candidates ================================
__global__ __launch_bounds__(256)
void k2g_gather() {
    const int b   = blockIdx.x >> 4;
    const int seg = blockIdx.x & 15;
    const int lane = threadIdx.x & 31;
    const unsigned thr = g_thr[b];
    const uint4* S4 = reinterpret_cast<const uint4*>(
        g_score + (size_t)b * NPRI + seg * SEGBOX);
    unsigned long long* cand = g_cand + (size_t)b * NPRI;
    const unsigned segbase = (unsigned)(seg * SEGBOX);

    #pragma unroll
    for (int t = 0; t < 2; t++) {
        int e = t * 256 + threadIdx.x;      // uint4 index within segment
        uint4 v = S4[e];
        unsigned base_i = segbase + (unsigned)e * 4u;
        #pragma unroll
        for (int q = 0; q < 4; q++) {
            unsigned u = (q == 0) ? v.x : (q == 1) ? v.y : (q == 2) ? v.z : v.w;
            bool p = (u >= thr);
            unsigned mask = __ballot_sync(0xffffffffu, p);
            if (mask) {
                int leader = __ffs(mask) - 1;
                int bp = 0;
                if (lane == leader) bp = atomicAdd(&g_ccnt[b], __popc(mask));
                bp = __shfl_sync(0xffffffffu, bp, leader);
                if (p) {
                    int off = bp + __popc(mask & ((1u << lane) - 1u));
                    cand[off] = ((unsigned long long)u << 32) |
                                (0xFFFFFFFFu - (base_i + (unsigned)q));
                }
            }
        }
    }
}

// ============ K2s: sort + decode -> box records =============================
__global__ __launch_bounds__(512)
void k2s_sort(const float* __restrict__ pred,
              const float* __restrict__ priors) {
    const int b   = blockIdx.x;
    const int tid = threadIdx.x;
    const float* P = pred + (size_t)b * NPRI * 6;
    unsigned long long* cand = g_cand + (size_t)b * NPRI;

    __shared__ unsigned long long s_top[512];
    __shared__ unsigned s_h[256];
    __shared__ int s_n, s_krem;
    __shared__ unsigned long long s_pv;

    const int cnt = g_ccnt[b];

    if (cnt <= 512) {
        s_top[tid] = (tid < cnt) ? cand[tid] : 0ull;
        __syncthreads();
    } else {
        // exact radix-select of 400th-largest over cand[0..cnt)
        if (tid == 0) { s_pv = 0ull; s_krem = TOPK; }
        __syncthreads();
        for (int byt = 7; byt >= 0; --byt) {
            if (tid < 256) s_h[tid] = 0;
            __syncthreads();
            unsigned long long pv = s_pv;
            unsigned long long hb =
                (byt == 7) ? 0ull : (0xFFFFFFFFFFFFFFFFull << ((byt + 1) * 8));
            for (int i = tid; i < cnt; i += 512) {
                unsigned long long e = cand[i];
                if (((e ^ pv) & hb) == 0)
                    atomicAdd(&s_h[(unsigned)((e >> (byt * 8)) & 255)], 1u);
            }
            __syncthreads();
            if (tid == 0) {
                unsigned acc = 0; int d = 255;
                for (; d >= 0; --d) {
                    if (acc + s_h[d] >= (unsigned)s_krem) break;
                    acc += s_h[d];
                }
                s_krem -= (int)acc;
                s_pv |= ((unsigned long long)(unsigned)d) << (byt * 8);
            }
            __syncthreads();
        }
        unsigned long long kth = s_pv;
        if (tid == 0) s_n = 0;
        __syncthreads();
        for (int i = tid; i < cnt; i += 512) {
            unsigned long long e = cand[i];
            if (e >= kth) {
                int p = atomicAdd(&s_n, 1);
                if (p < 512) s_top[p] = e;
            }
        }
        __syncthreads();
        int n = s_n;
        if (tid >= n) s_top[tid] = 0ull;
        __syncthreads();
    }

    // bitonic sort 512 DESC
    for (int ksz = 2; ksz <= 512; ksz <<= 1)
        for (int j = ksz >> 1; j > 0; j >>= 1) {
            int ixj = tid ^ j;
            if (ixj > tid) {
                unsigned long long a = s_top[tid], c = s_top[ixj];
                bool sw = ((tid & ksz) == 0) ? (a < c) : (a > c);
                if (sw) { s_top[tid] = c; s_top[ixj] = a; }
            }
            __syncthreads();
        }

    // decode + store records
    if (tid < TOPK) {
        unsigned long long key = s_top[tid];
        unsigned u = (unsigned)(key >> 32);
        float sc = unorder_f(u);
        unsigned idxu = 0xFFFFFFFFu - (unsigned)(key & 0xFFFFFFFFull);
        int idx = (int)min(idxu, (unsigned)(NPRI - 1));
        const float* pp = P + 6 * idx;
        float l0 = pp[0], l1 = pp[1], l2 = pp[2], l3 = pp[3];
        float c0 = pp[4], c1 = pp[5];
        float4 pr = *reinterpret_cast<const float4*>(priors + 4 * idx);
        float cx = __fadd_rn(pr.x, __fmul_rn(__fmul_rn(l0, 0.1f), pr.z));
        float cy = __fadd_rn(pr.y, __fmul_rn(__fmul_rn(l1, 0.1f), pr.w));
        float w  = __fmul_rn(pr.z, expf(__fmul_rn(l2, 0.2f)));
        float h  = __fmul_rn(pr.w, expf(__fmul_rn(l3, 0.2f)));
        float x1 = __fsub_rn(cx, __fmul_rn(w, 0.5f));
        float y1 = __fsub_rn(cy, __fmul_rn(h, 0.5f));
        float x2 = __fadd_rn(cx, __fmul_rn(w, 0.5f));
        float y2 = __fadd_rn(cy, __fmul_rn(h, 0.5f));
        float ar = __fmul_rn(__fsub_rn(x2, x1), __fsub_rn(y2, y1));
        g_box4[b * TOPK + tid] = make_float4(x1, y1, x2, y2);
        g_aux[b * TOPK + tid]  = make_float4(ar, sc, (c1 > c0) ? 1.0f : 0.0f, 0.0f);
    }
}

// ============ K3b: suppression masks, one 32-wide j-column per block ========
__global__ __launch_bounds__(256)
void k3b_mask() {
    const int jb = blockIdx.x;            // 0..12
    const int b  = blockIdx.y;
    const int lane = threadIdx.x & 31;
    const int wid  = threadIdx.x >> 5;    // 0..7

    __shared__ float s_x1[TOPK], s_y1[TOPK], s_x2[TOPK], s_y2[TOPK], s_ar[TOPK];
    for (int i = threadIdx.x; i < TOPK; i += 256) {
        float4 bb = g_box4[b * TOPK + i];
        s_x1[i] = bb.x; s_y1[i] = bb.y; s_x2[i] = bb.z; s_y2[i] = bb.w;
        s_ar[i] = g_aux[b * TOPK + i].x;
    }
    __syncthreads();

    int j = jb * 32 + lane;
    bool jv = (j < TOPK);
    float jx1 = jv ? s_x1[j] : 0.f, jy1 = jv ? s_y1[j] : 0.f;
    float jx2 = jv ? s_x2[j] : 0.f, jy2 = jv ? s_y2[j] : 0.f;
    float jar = jv ? s_ar[j] : 0.f;

    const int rows = min(TOPK, (jb + 1) * 32);
    unsigned* outw = g_sup + ((size_t)b * TOPK) * WORDS;
    for (int i = wid; i < rows; i += 8) {
        float bx1 = s_x1[i], by1 = s_y1[i];
        float bx2 = s_x2[i], by2 = s_y2[i];
        float bar = s_ar[i];
        bool sbit = false;
        if (jv && j > i) {
            float iw = fmaxf(__fsub_rn(fminf(jx2, bx2), fmaxf(jx1, bx1)), 0.0f);
            float ih = fmaxf(__fsub_rn(fminf(jy2, by2), fmaxf(jy1, by1)), 0.0f);
            float inter = __fmul_rn(iw, ih);
            float den = __fadd_rn(__fsub_rn(__fadd_rn(bar, jar), inter), 1e-12f);
            sbit = (__fdiv_rn(inter, den) > NMS_T);
        }
        unsigned wd = __ballot_sync(0xffffffffu, sbit);
        if (lane == 0) outw[i * WORDS + jb] = wd;
    }
}

// ============ K3c: greedy NMS + rank + emit =================================
__global__ __launch_bounds__(512)
void k3c_final(float* __restrict__ out) {
    const int b    = blockIdx.x;
    const int tid  = threadIdx.x;
    const int lane = tid & 31;
    const int wid  = tid >> 5;

    __shared__ unsigned s_sup[TOPK * WORDS];
    __shared__ float s_x1[TOPK], s_y1[TOPK], s_x2[TOPK], s_y2[TOPK];
    __shared__ float s_sc[TOPK], s_lab[TOPK];
    __shared__ unsigned s_keep[WORDS], s_act[WORDS];
    __shared__ int s_nkeep;

    const unsigned* supg = g_sup + ((size_t)b * TOPK) * WORDS;
    for (int i = tid; i < TOPK * WORDS; i += 512) s_sup[i] = supg[i];
    for (int i = tid; i < TOPK; i += 512) {
        float4 bb = g_box4[b * TOPK + i];
        s_x1[i] = bb.x; s_y1[i] = bb.y; s_x2[i] = bb.z; s_y2[i] = bb.w;
        float4 ax = g_aux[b * TOPK + i];
        s_sc[i] = ax.y; s_lab[i] = ax.z;
    }
    __syncthreads();

    if (tid < WORDS * 32) {
        bool a = false;
        if (tid < TOPK) {
            unsigned o = 0;
            for (int w = tid >> 5; w < WORDS; w++) o |= s_sup[tid * WORDS + w];
            a = (o != 0);
        }
        unsigned ma = __ballot_sync(0xffffffffu, a);
        bool v = (tid < TOPK) && (s_sc[tid] > CONF_T);
        unsigned mk = __ballot_sync(0xffffffffu, v);
        if (lane == 0) { s_act[wid] = ma; s_keep[wid] = mk; }
    }
    __syncthreads();

    // greedy: warp 0, lane w owns word w
    if (wid == 0) {
        unsigned kp = (lane < WORDS) ? s_keep[lane] : 0u;
        unsigned rm = (lane < WORDS) ? (kp & s_act[lane]) : 0u;
        for (;;) {
            int cnd = rm ? (lane * 32 + __ffs(rm) - 1) : 0x7FFFFFFF;
            int i = (int)__reduce_min_sync(0xffffffffu, (unsigned)cnd);
            if (i == 0x7FFFFFFF) break;
            if (lane == (i >> 5)) rm &= ~(1u << (i & 31));
            unsigned s = (lane < WORDS && lane >= (i >> 5))
                         ? s_sup[i * WORDS + lane] : 0u;
            kp &= ~s; rm &= ~s;
        }
        if (lane < WORDS) s_keep[lane] = kp;
        int nk = __popc(kp);
        #pragma unroll
        for (int d = 16; d; d >>= 1) nk += __shfl_xor_sync(0xffffffffu, nk, d);
        if (lane == 0) s_nkeep = nk;
    }
    __syncthreads();

    // rank + emit
    {
        float* ob = out + (size_t)b * (KEEPK * 6);
        const int nkeep = s_nkeep;
        const int nk = min(nkeep, KEEPK);
        if (tid >= nk && tid < KEEPK) {
            #pragma unroll
            for (int q = 0; q < 6; q++) ob[tid * 6 + q] = 0.0f;
        }
        if (tid < TOPK) {
            bool kept = (s_keep[tid >> 5] >> (tid & 31)) & 1u;
            if (kept) {
                float sc = s_sc[tid];
                int p = 0;
                int wi = tid >> 5;
                for (int w = 0; w < wi; w++) p += __popc(s_keep[w]);
                p += __popc(s_keep[wi] & ((1u << (tid & 31)) - 1u));
                int sct = 0;
                for (int j = tid - 1; j >= 0 && s_sc[j] == sc; --j)
                    if ((s_keep[j >> 5] >> (j & 31)) & 1u) sct++;
                int ect = 0;
                for (int j = tid + 1; j < TOPK && s_sc[j] == sc; ++j)
                    if ((s_keep[j >> 5] >> (j & 31)) & 1u) ect++;
                int r = (nkeep - (p + ect + 1)) + sct;
                if (r < KEEPK) {
                    ob[r * 6 + 0] = s_lab[tid];
                    ob[r * 6 + 1] = sc;
                    ob[r * 6 + 2] = s_x1[tid];
                    ob[r * 6 + 3] = s_y1[tid];
                    ob[r * 6 + 4] = s_x2[tid];
                    ob[r * 6 + 5] = s_y2[tid];
                }
            }
        }
    }
}

extern "C" void kernel_launch(void* const* d_in, const int* in_sizes, int n_in,
                              void* d_out, int out_size) {
    const float* pred   = (const float*)d_in[0];
    const float* priors = (const float*)d_in[1];
    int nb = in_sizes[0] / (NPRI * 6);
    if (nb <= 0 || nb > NB) nb = NB;
    k1_score<<<nb * SEGS, 256>>>(pred);
    k2t_thresh<<<nb, 512>>>();
    k2g_gather<<<nb * SEGS, 256>>>();
    k2s_sort<<<nb, 512>>>(pred, priors);
    k3b_mask<<<dim3(WORDS, nb), 256>>>();
    k3c_final<<<nb, 512>>>((float*)d_out);
}

// round 14
// speedup vs baseline: 1.2119x; 1.2119x over previous
#include <cuda_runtime.h>
#include <cstdint>

#define NB    128
#define NPRI  32768
#define TOPK  400
#define KEEPK 200
#define WORDS 13
#define CONF_T 0.5f
#define NMS_T  0.5f
#define BIGNEG -1000000000.0f
#define HBINS 512
#define HBASE 12224u          // order_f(0.5) >> 18
#define SEGS  16
#define SEGBOX (NPRI / SEGS)

__device__ unsigned           g_score[NB * NPRI];
__device__ unsigned long long g_cand[NB * NPRI];   // per-(image,segment) regions
__device__ unsigned           g_hist[NB * HBINS];
__device__ unsigned           g_thr[NB];
__device__ int                g_scnt[NB * SEGS];
__device__ float4             g_box4[NB * TOPK];   // x1,y1,x2,y2
__device__ float4             g_aux[NB * TOPK];    // area, score, label, 0
__device__ unsigned           g_sup[NB * TOPK * WORDS];

__device__ __forceinline__ unsigned order_f(float f) {
    unsigned u = __float_as_uint(f);
    return (u & 0x80000000u) ? ~u : (u | 0x80000000u);
}
__device__ __forceinline__ float unorder_f(unsigned u) {
    unsigned v = (u & 0x80000000u) ? (u ^ 0x80000000u) : ~u;
    return __uint_as_float(v);
}

// ============ K1: stream pred, emit ordered scores + 512-bin histogram ======
__global__ __launch_bounds__(256)
void k1_score(const float* __restrict__ pred) {
    const int b   = blockIdx.x >> 4;
    const int seg = blockIdx.x & 15;
    __shared__ unsigned sh[HBINS];
    sh[threadIdx.x] = 0; sh[threadIdx.x + 256] = 0;
    __syncthreads();

    const float4* P4 = reinterpret_cast<const float4*>(
        pred + (size_t)b * NPRI * 6 + (size_t)seg * SEGBOX * 6);
    uint2* S2 = reinterpret_cast<uint2*>(g_score + (size_t)b * NPRI + seg * SEGBOX);

    #pragma unroll
    for (int it = 0; it < 4; it++) {
        int e = it * 256 + threadIdx.x;
        float4 a1 = P4[3 * e + 1];
        float4 a2 = P4[3 * e + 2];
        float s0 = fmaxf(a1.x, a1.y);
        float s1 = fmaxf(a2.z, a2.w);
        unsigned u0 = order_f((s0 > CONF_T) ? s0 : BIGNEG);
        unsigned u1 = order_f((s1 > CONF_T) ? s1 : BIGNEG);
        S2[e] = make_uint2(u0, u1);
        if (s0 > CONF_T) atomicAdd(&sh[min(511u, (u0 >> 18) - HBASE)], 1u);
        if (s1 > CONF_T) atomicAdd(&sh[min(511u, (u1 >> 18) - HBASE)], 1u);
    }
    __syncthreads();
    #pragma unroll
    for (int i = threadIdx.x; i < HBINS; i += 256) {
        unsigned v = sh[i];
        if (v) atomicAdd(&g_hist[b * HBINS + i], v);
    }
}

// ============ K2t: per-image threshold from histogram =======================
__global__ __launch_bounds__(512)
void k2t_thresh() {
    const int b = blockIdx.x;
    const int tid = threadIdx.x;
    __shared__ unsigned s_ss[HBINS];
    __shared__ int s_v;
    s_ss[tid] = g_hist[b * HBINS + tid];
    g_hist[b * HBINS + tid] = 0;            // reset for next replay
    if (tid == 0) s_v = 0;
    __syncthreads();
    for (int d = 1; d < HBINS; d <<= 1) {
        unsigned v = (tid + d < HBINS) ? s_ss[tid + d] : 0u;
        __syncthreads();
        s_ss[tid] += v;
        __syncthreads();
    }
    {
        bool hit = (s_ss[tid] >= TOPK) && (tid == HBINS - 1 || s_ss[tid + 1] < TOPK);
        if (hit) s_v = tid;
    }
    __syncthreads();
    if (tid == 0) g_thr[b] = (HBASE + (unsigned)s_v) << 18;
}

// ============ K2g: gather into per-segment regions (no global atomics) ======
__global__ __launch_bounds__(256)
void k2g_gather() {
    const int b   = blockIdx.x >> 4;
    const int seg = blockIdx.x & 15;
    const unsigned thr = g_thr[b];
    const uint4* S4 = reinterpret_cast<const uint4*>(
        g_score + (size_t)b * NPRI + seg * SEGBOX);
    unsigned long long* my = g_cand + (size_t)b * NPRI + (size_t)seg * SEGBOX;
    const unsigned segbase = (unsigned)(seg * SEGBOX);

    __shared__ int s_cnt;
    if (threadIdx.x == 0) s_cnt = 0;
    __syncthreads();

    #pragma unroll
    for (int t = 0; t < 2; t++) {
        int e = t * 256 + threadIdx.x;      // uint4 index within segment
        uint4 v = S4[e];
        unsigned base_i = segbase + (unsigned)e * 4u;
        #pragma unroll
        for (int q = 0; q < 4; q++) {
            unsigned u = (q == 0) ? v.x : (q == 1) ? v.y : (q == 2) ? v.z : v.w;
            if (u >= thr) {
                int pos = atomicAdd(&s_cnt, 1);
                my[pos] = ((unsigned long long)u << 32) |
                          (0xFFFFFFFFu - (base_i + (unsigned)q));
            }
        }
    }
    __syncthreads();
    if (threadIdx.x == 0) g_scnt[b * SEGS + seg] = s_cnt;
}

// ============ K2s: merge segments + sort + decode -> box records ============
__global__ __launch_bounds__(512)
void k2s_sort(const float* __restrict__ pred,
              const float* __restrict__ priors) {
    const int b   = blockIdx.x;
    const int tid = threadIdx.x;
    const float* P = pred + (size_t)b * NPRI * 6;
    const unsigned long long* cand = g_cand + (size_t)b * NPRI;

    __shared__ unsigned long long s_top[512];
    __shared__ unsigned s_h[256];
    __shared__ int s_pre[SEGS + 1];
    __shared__ int s_n, s_krem;
    __shared__ unsigned long long s_pv;

    // segment counts -> prefix
    if (tid == 0) {
        int acc = 0;
        #pragma unroll
        for (int s = 0; s < SEGS; s++) {
            s_pre[s] = acc;
            acc += g_scnt[b * SEGS + s];
        }
        s_pre[SEGS] = acc;
    }
    __syncthreads();
    const int cnt = s_pre[SEGS];

    if (cnt <= 512) {
        unsigned long long key = 0ull;
        if (tid < cnt) {
            int s = 0;
            #pragma unroll
            for (int q = 1; q < SEGS; q++) if (tid >= s_pre[q]) s = q;
            key = cand[(size_t)s * SEGBOX + (tid - s_pre[s])];
        }
        s_top[tid] = key;
        __syncthreads();
    } else {
        // exact radix-select of 400th-largest over all segment regions
        if (tid == 0) { s_pv = 0ull; s_krem = TOPK; }
        __syncthreads();
        for (int byt = 7; byt >= 0; --byt) {
            if (tid < 256) s_h[tid] = 0;
            __syncthreads();
            unsigned long long pv = s_pv;
            unsigned long long hb =
                (byt == 7) ? 0ull : (0xFFFFFFFFFFFFFFFFull << ((byt + 1) * 8));
            for (int s = 0; s < SEGS; s++) {
                int c = s_pre[s + 1] - s_pre[s];
                for (int i = tid; i < c; i += 512) {
                    unsigned long long e = cand[(size_t)s * SEGBOX + i];
                    if (((e ^ pv) & hb) == 0)
                        atomicAdd(&s_h[(unsigned)((e >> (byt * 8)) & 255)], 1u);
                }
            }
            __syncthreads();
            if (tid == 0) {
                unsigned acc = 0; int d = 255;
                for (; d >= 0; --d) {
                    if (acc + s_h[d] >= (unsigned)s_krem) break;
                    acc += s_h[d];
                }
                s_krem -= (int)acc;
                s_pv |= ((unsigned long long)(unsigned)d) << (byt * 8);
            }
            __syncthreads();
        }
        unsigned long long kth = s_pv;
        if (tid == 0) s_n = 0;
        __syncthreads();
        for (int s = 0; s < SEGS; s++) {
            int c = s_pre[s + 1] - s_pre[s];
            for (int i = tid; i < c; i += 512) {
                unsigned long long e = cand[(size_t)s * SEGBOX + i];
                if (e >= kth) {
                    int p = atomicAdd(&s_n, 1);
                    if (p < 512) s_top[p] = e;
                }
            }
        }
        __syncthreads();
        int n = s_n;
        if (tid >= n) s_top[tid] = 0ull;
        __syncthreads();
    }

    // bitonic sort 512 DESC
    for (int ksz = 2; ksz <= 512; ksz <<= 1)
        for (int j = ksz >> 1; j > 0; j >>= 1) {
            int ixj = tid ^ j;
            if (ixj > tid) {
                unsigned long long a = s_top[tid], c = s_top[ixj];
                bool sw = ((tid & ksz) == 0) ? (a < c) : (a > c);
                if (sw) { s_top[tid] = c; s_top[ixj] = a; }
            }
            __syncthreads();
        }

    // decode + store records
    if (tid < TOPK) {
        unsigned long long key = s_top[tid];
        unsigned u = (unsigned)(key >> 32);
        float sc = unorder_f(u);
        unsigned idxu = 0xFFFFFFFFu - (unsigned)(key & 0xFFFFFFFFull);
        int idx = (int)min(idxu, (unsigned)(NPRI - 1));
        const float* pp = P + 6 * idx;
        float l0 = pp[0], l1 = pp[1], l2 = pp[2], l3 = pp[3];
        float c0 = pp[4], c1 = pp[5];
        float4 pr = *reinterpret_cast<const float4*>(priors + 4 * idx);
        float cx = __fadd_rn(pr.x, __fmul_rn(__fmul_rn(l0, 0.1f), pr.z));
        float cy = __fadd_rn(pr.y, __fmul_rn(__fmul_rn(l1, 0.1f), pr.w));
        float w  = __fmul_rn(pr.z, expf(__fmul_rn(l2, 0.2f)));
        float h  = __fmul_rn(pr.w, expf(__fmul_rn(l3, 0.2f)));
        float x1 = __fsub_rn(cx, __fmul_rn(w, 0.5f));
        float y1 = __fsub_rn(cy, __fmul_rn(h, 0.5f));
        float x2 = __fadd_rn(cx, __fmul_rn(w, 0.5f));
        float y2 = __fadd_rn(cy, __fmul_rn(h, 0.5f));
        float ar = __fmul_rn(__fsub_rn(x2, x1), __fsub_rn(y2, y1));
        g_box4[b * TOPK + tid] = make_float4(x1, y1, x2, y2);
        g_aux[b * TOPK + tid]  = make_float4(ar, sc, (c1 > c0) ? 1.0f : 0.0f, 0.0f);
    }
}

// ============ K3b: suppression masks, one 32-wide j-column per block ========
__global__ __launch_bounds__(256)
void k3b_mask() {
    const int jb = blockIdx.x;            // 0..12
    const int b  = blockIdx.y;
    const int lane = threadIdx.x & 31;
    const int wid  = threadIdx.x >> 5;    // 0..7

    __shared__ float s_x1[TOPK], s_y1[TOPK], s_x2[TOPK], s_y2[TOPK], s_ar[TOPK];
    for (int i = threadIdx.x; i < TOPK; i += 256) {
        float4 bb = g_box4[b * TOPK + i];
        s_x1[i] = bb.x; s_y1[i] = bb.y; s_x2[i] = bb.z; s_y2[i] = bb.w;
        s_ar[i] = g_aux[b * TOPK + i].x;
    }
    __syncthreads();

    int j = jb * 32 + lane;
    bool jv = (j < TOPK);
    float jx1 = jv ? s_x1[j] : 0.f, jy1 = jv ? s_y1[j] : 0.f;
    float jx2 = jv ? s_x2[j] : 0.f, jy2 = jv ? s_y2[j] : 0.f;
    float jar = jv ? s_ar[j] : 0.f;

    const int rows = min(TOPK, (jb + 1) * 32);
    unsigned* outw = g_sup + ((size_t)b * TOPK) * WORDS;
    for (int i = wid; i < rows; i += 8) {
        float bx1 = s_x1[i], by1 = s_y1[i];
        float bx2 = s_x2[i], by2 = s_y2[i];
        float bar = s_ar[i];
        bool sbit = false;
        if (jv && j > i) {
            float iw = fmaxf(__fsub_rn(fminf(jx2, bx2), fmaxf(jx1, bx1)), 0.0f);
            float ih = fmaxf(__fsub_rn(fminf(jy2, by2), fmaxf(jy1, by1)), 0.0f);
            float inter = __fmul_rn(iw, ih);
            float den = __fadd_rn(__fsub_rn(__fadd_rn(bar, jar), inter), 1e-12f);
            sbit = (__fdiv_rn(inter, den) > NMS_T);
        }
        unsigned wd = __ballot_sync(0xffffffffu, sbit);
        if (lane == 0) outw[i * WORDS + jb] = wd;
    }
}

// ============ K3c: greedy NMS + rank + emit =================================
__global__ __launch_bounds__(512)
void k3c_final(float* __restrict__ out) {
    const int b    = blockIdx.x;
    const int tid  = threadIdx.x;
    const int lane = tid & 31;
    const int wid  = tid >> 5;

    __shared__ unsigned s_sup[TOPK * WORDS];
    __shared__ float s_x1[TOPK], s_y1[TOPK], s_x2[TOPK], s_y2[TOPK];
    __shared__ float s_sc[TOPK], s_lab[TOPK];
    __shared__ unsigned s_keep[WORDS], s_act[WORDS];
    __shared__ int s_nkeep;

    const unsigned* supg = g_sup + ((size_t)b * TOPK) * WORDS;
    for (int i = tid; i < TOPK * WORDS; i += 512) s_sup[i] = supg[i];
    for (int i = tid; i < TOPK; i += 512) {
        float4 bb = g_box4[b * TOPK + i];
        s_x1[i] = bb.x; s_y1[i] = bb.y; s_x2[i] = bb.z; s_y2[i] = bb.w;
        float4 ax = g_aux[b * TOPK + i];
        s_sc[i] = ax.y; s_lab[i] = ax.z;
    }
    __syncthreads();

    if (tid < WORDS * 32) {
        bool a = false;
        if (tid < TOPK) {
            unsigned o = 0;
            for (int w = tid >> 5; w < WORDS; w++) o |= s_sup[tid * WORDS + w];
            a = (o != 0);
        }
        unsigned ma = __ballot_sync(0xffffffffu, a);
        bool v = (tid < TOPK) && (s_sc[tid] > CONF_T);
        unsigned mk = __ballot_sync(0xffffffffu, v);
        if (lane == 0) { s_act[wid] = ma; s_keep[wid] = mk; }
    }
    __syncthreads();

    // greedy: warp 0, lane w owns word w
    if (wid == 0) {
        unsigned kp = (lane < WORDS) ? s_keep[lane] : 0u;
        unsigned rm = (lane < WORDS) ? (kp & s_act[lane]) : 0u;
        for (;;) {
            int cnd = rm ? (lane * 32 + __ffs(rm) - 1) : 0x7FFFFFFF;
            int i = (int)__reduce_min_sync(0xffffffffu, (unsigned)cnd);
            if (i == 0x7FFFFFFF) break;
            if (lane == (i >> 5)) rm &= ~(1u << (i & 31));
            unsigned s = (lane < WORDS && lane >= (i >> 5))
                         ? s_sup[i * WORDS + lane] : 0u;
            kp &= ~s; rm &= ~s;
        }
        if (lane < WORDS) s_keep[lane] = kp;
        int nk = __popc(kp);
        #pragma unroll
        for (int d = 16; d; d >>= 1) nk += __shfl_xor_sync(0xffffffffu, nk, d);
        if (lane == 0) s_nkeep = nk;
    }
    __syncthreads();

    // rank + emit
    {
        float* ob = out + (size_t)b * (KEEPK * 6);
        const int nkeep = s_nkeep;
        const int nk = min(nkeep, KEEPK);
        if (tid >= nk && tid < KEEPK) {
            #pragma unroll
            for (int q = 0; q < 6; q++) ob[tid * 6 + q] = 0.0f;
        }
        if (tid < TOPK) {
            bool kept = (s_keep[tid >> 5] >> (tid & 31)) & 1u;
            if (kept) {
                float sc = s_sc[tid];
                int p = 0;
                int wi = tid >> 5;
                for (int w = 0; w < wi; w++) p += __popc(s_keep[w]);
                p += __popc(s_keep[wi] & ((1u << (tid & 31)) - 1u));
                int sct = 0;
                for (int j = tid - 1; j >= 0 && s_sc[j] == sc; --j)
                    if ((s_keep[j >> 5] >> (j & 31)) & 1u) sct++;
                int ect = 0;
                for (int j = tid + 1; j < TOPK && s_sc[j] == sc; ++j)
                    if ((s_keep[j >> 5] >> (j & 31)) & 1u) ect++;
                int r = (nkeep - (p + ect + 1)) + sct;
                if (r < KEEPK) {
                    ob[r * 6 + 0] = s_lab[tid];
                    ob[r * 6 + 1] = sc;
                    ob[r * 6 + 2] = s_x1[tid];
                    ob[r * 6 + 3] = s_y1[tid];
                    ob[r * 6 + 4] = s_x2[tid];
                    ob[r * 6 + 5] = s_y2[tid];
                }
            }
        }
    }
}

extern "C" void kernel_launch(void* const* d_in, const int* in_sizes, int n_in,
                              void* d_out, int out_size) {
    const float* pred   = (const float*)d_in[0];
    const float* priors = (const float*)d_in[1];
    int nb = in_sizes[0] / (NPRI * 6);
    if (nb <= 0 || nb > NB) nb = NB;
    k1_score<<<nb * SEGS, 256>>>(pred);
    k2t_thresh<<<nb, 512>>>();
    k2g_gather<<<nb * SEGS, 256>>>();
    k2s_sort<<<nb, 512>>>(pred, priors);
    k3b_mask<<<dim3(WORDS, nb), 256>>>();
    k3c_final<<<nb, 512>>>((float*)d_out);
}

// round 16
// speedup vs baseline: 1.2394x; 1.0227x over previous
#include <cuda_runtime.h>
#include <cstdint>

#define NB    128
#define NPRI  32768
#define TOPK  400
#define KEEPK 200
#define WORDS 13
#define CONF_T 0.5f
#define NMS_T  0.5f
#define BIGNEG -1000000000.0f
#define HBINS 512
#define HBASE 12224u          // order_f(0.5) >> 18
#define SEGS  16
#define SEGBOX (NPRI / SEGS)
#define GTOT  2896            // sum_{jb=0..12} min(400,(jb+1)*32)
#define GPW   91              // ceil(GTOT/32)

__device__ unsigned           g_score[NB * NPRI];
__device__ unsigned long long g_cand[NB * NPRI];   // per-(image,segment) regions
__device__ unsigned           g_hist[NB * HBINS];
__device__ int                g_scnt[NB * SEGS];
__device__ float4             g_box4[NB * TOPK];   // x1,y1,x2,y2
__device__ float4             g_aux[NB * TOPK];    // area, score, label, 0

__device__ __forceinline__ unsigned order_f(float f) {
    unsigned u = __float_as_uint(f);
    return (u & 0x80000000u) ? ~u : (u | 0x80000000u);
}
__device__ __forceinline__ float unorder_f(unsigned u) {
    unsigned v = (u & 0x80000000u) ? (u ^ 0x80000000u) : ~u;
    return __uint_as_float(v);
}

// ============ K1: stream pred, emit ordered scores + 512-bin histogram ======
__global__ __launch_bounds__(256)
void k1_score(const float* __restrict__ pred) {
    const int b   = blockIdx.x >> 4;
    const int seg = blockIdx.x & 15;
    __shared__ unsigned sh[HBINS];
    sh[threadIdx.x] = 0; sh[threadIdx.x + 256] = 0;
    __syncthreads();

    const float4* P4 = reinterpret_cast<const float4*>(
        pred + (size_t)b * NPRI * 6 + (size_t)seg * SEGBOX * 6);
    uint2* S2 = reinterpret_cast<uint2*>(g_score + (size_t)b * NPRI + seg * SEGBOX);

    #pragma unroll
    for (int it = 0; it < 4; it++) {
        int e = it * 256 + threadIdx.x;
        float4 a1 = P4[3 * e + 1];
        float4 a2 = P4[3 * e + 2];
        float s0 = fmaxf(a1.x, a1.y);
        float s1 = fmaxf(a2.z, a2.w);
        unsigned u0 = order_f((s0 > CONF_T) ? s0 : BIGNEG);
        unsigned u1 = order_f((s1 > CONF_T) ? s1 : BIGNEG);
        S2[e] = make_uint2(u0, u1);
        if (s0 > CONF_T) atomicAdd(&sh[min(511u, (u0 >> 18) - HBASE)], 1u);
        if (s1 > CONF_T) atomicAdd(&sh[min(511u, (u1 >> 18) - HBASE)], 1u);
    }
    __syncthreads();
    #pragma unroll
    for (int i = threadIdx.x; i < HBINS; i += 256) {
        unsigned v = sh[i];
        if (v) atomicAdd(&g_hist[b * HBINS + i], v);
    }
}

// ===== K2g: per-block threshold recompute + gather into segment regions =====
__global__ __launch_bounds__(512)
void k2g_gather() {
    const int b   = blockIdx.x >> 4;
    const int seg = blockIdx.x & 15;
    const int tid = threadIdx.x;

    __shared__ unsigned s_ss[HBINS];
    __shared__ int s_v, s_cnt;

    // threshold from histogram (deterministic, identical across the 16 blocks)
    s_ss[tid] = g_hist[b * HBINS + tid];
    if (tid == 0) { s_v = 0; s_cnt = 0; }
    __syncthreads();
    for (int d = 1; d < HBINS; d <<= 1) {
        unsigned v = (tid + d < HBINS) ? s_ss[tid + d] : 0u;
        __syncthreads();
        s_ss[tid] += v;
        __syncthreads();
    }
    {
        bool hit = (s_ss[tid] >= TOPK) && (tid == HBINS - 1 || s_ss[tid + 1] < TOPK);
        if (hit) s_v = tid;
    }
    __syncthreads();
    const unsigned thr = (HBASE + (unsigned)s_v) << 18;

    // gather: 1 uint4 per thread, shared-counter append (no global atomics)
    const uint4* S4 = reinterpret_cast<const uint4*>(
        g_score + (size_t)b * NPRI + seg * SEGBOX);
    unsigned long long* my = g_cand + (size_t)b * NPRI + (size_t)seg * SEGBOX;
    const unsigned segbase = (unsigned)(seg * SEGBOX);

    uint4 v = S4[tid];
    unsigned base_i = segbase + (unsigned)tid * 4u;
    #pragma unroll
    for (int q = 0; q < 4; q++) {
        unsigned u = (q == 0) ? v.x : (q == 1) ? v.y : (q == 2) ? v.z : v.w;
        if (u >= thr) {
            int pos = atomicAdd(&s_cnt, 1);
            my[pos] = ((unsigned long long)u << 32) |
                      (0xFFFFFFFFu - (base_i + (unsigned)q));
        }
    }
    __syncthreads();
    if (tid == 0) g_scnt[b * SEGS + seg] = s_cnt;
}

// ============ K2s: merge segments + sort + decode -> box records ============
__global__ __launch_bounds__(512)
void k2s_sort(const float* __restrict__ pred,
              const float* __restrict__ priors) {
    const int b   = blockIdx.x;
    const int tid = threadIdx.x;
    const float* P = pred + (size_t)b * NPRI * 6;
    const unsigned long long* cand = g_cand + (size_t)b * NPRI;

    __shared__ unsigned long long s_top[512];
    __shared__ unsigned s_h[256];
    __shared__ int s_pre[SEGS + 1];
    __shared__ int s_n, s_krem;
    __shared__ unsigned long long s_pv;

    g_hist[b * HBINS + tid] = 0;            // reset for next graph replay

    if (tid == 0) {
        int acc = 0;
        #pragma unroll
        for (int s = 0; s < SEGS; s++) {
            s_pre[s] = acc;
            acc += g_scnt[b * SEGS + s];
        }
        s_pre[SEGS] = acc;
    }
    __syncthreads();
    const int cnt = s_pre[SEGS];

    if (cnt <= 512) {
        unsigned long long key = 0ull;
        if (tid < cnt) {
            int s = 0;
            #pragma unroll
            for (int q = 1; q < SEGS; q++) if (tid >= s_pre[q]) s = q;
            key = cand[(size_t)s * SEGBOX + (tid - s_pre[s])];
        }
        s_top[tid] = key;
        __syncthreads();
    } else {
        // exact radix-select of 400th-largest over all segment regions
        if (tid == 0) { s_pv = 0ull; s_krem = TOPK; }
        __syncthreads();
        for (int byt = 7; byt >= 0; --byt) {
            if (tid < 256) s_h[tid] = 0;
            __syncthreads();
            unsigned long long pv = s_pv;
            unsigned long long hb =
                (byt == 7) ? 0ull : (0xFFFFFFFFFFFFFFFFull << ((byt + 1) * 8));
            for (int s = 0; s < SEGS; s++) {
                int c = s_pre[s + 1] - s_pre[s];
                for (int i = tid; i < c; i += 512) {
                    unsigned long long e = cand[(size_t)s * SEGBOX + i];
                    if (((e ^ pv) & hb) == 0)
                        atomicAdd(&s_h[(unsigned)((e >> (byt * 8)) & 255)], 1u);
                }
            }
            __syncthreads();
            if (tid == 0) {
                unsigned acc = 0; int d = 255;
                for (; d >= 0; --d) {
                    if (acc + s_h[d] >= (unsigned)s_krem) break;
                    acc += s_h[d];
                }
                s_krem -= (int)acc;
                s_pv |= ((unsigned long long)(unsigned)d) << (byt * 8);
            }
            __syncthreads();
        }
        unsigned long long kth = s_pv;
        if (tid == 0) s_n = 0;
        __syncthreads();
        for (int s = 0; s < SEGS; s++) {
            int c = s_pre[s + 1] - s_pre[s];
            for (int i = tid; i < c; i += 512) {
                unsigned long long e = cand[(size_t)s * SEGBOX + i];
                if (e >= kth) {
                    int p = atomicAdd(&s_n, 1);
                    if (p < 512) s_top[p] = e;
                }
            }
        }
        __syncthreads();
        int n = s_n;
        if (tid >= n) s_top[tid] = 0ull;
        __syncthreads();
    }

    // bitonic sort 512 DESC
    for (int ksz = 2; ksz <= 512; ksz <<= 1)
        for (int j = ksz >> 1; j > 0; j >>= 1) {
            int ixj = tid ^ j;
            if (ixj > tid) {
                unsigned long long a = s_top[tid], c = s_top[ixj];
                bool sw = ((tid & ksz) == 0) ? (a < c) : (a > c);
                if (sw) { s_top[tid] = c; s_top[ixj] = a; }
            }
            __syncthreads();
        }

    // decode + store records
    if (tid < TOPK) {
        unsigned long long key = s_top[tid];
        unsigned u = (unsigned)(key >> 32);
        float sc = unorder_f(u);
        unsigned idxu = 0xFFFFFFFFu - (unsigned)(key & 0xFFFFFFFFull);
        int idx = (int)min(idxu, (unsigned)(NPRI - 1));
        const float* pp = P + 6 * idx;
        float l0 = pp[0], l1 = pp[1], l2 = pp[2], l3 = pp[3];
        float c0 = pp[4], c1 = pp[5];
        float4 pr = *reinterpret_cast<const float4*>(priors + 4 * idx);
        float cx = __fadd_rn(pr.x, __fmul_rn(__fmul_rn(l0, 0.1f), pr.z));
        float cy = __fadd_rn(pr.y, __fmul_rn(__fmul_rn(l1, 0.1f), pr.w));
        float w  = __fmul_rn(pr.z, expf(__fmul_rn(l2, 0.2f)));
        float h  = __fmul_rn(pr.w, expf(__fmul_rn(l3, 0.2f)));
        float x1 = __fsub_rn(cx, __fmul_rn(w, 0.5f));
        float y1 = __fsub_rn(cy, __fmul_rn(h, 0.5f));
        float x2 = __fadd_rn(cx, __fmul_rn(w, 0.5f));
        float y2 = __fadd_rn(cy, __fmul_rn(h, 0.5f));
        float ar = __fmul_rn(__fsub_rn(x2, x1), __fsub_rn(y2, y1));
        g_box4[b * TOPK + tid] = make_float4(x1, y1, x2, y2);
        g_aux[b * TOPK + tid]  = make_float4(ar, sc, (c1 > c0) ? 1.0f : 0.0f, 0.0f);
    }
}

// ====== K3c: masks (smem) + greedy NMS + rank + emit, one block/image =======
__global__ __launch_bounds__(1024)
void k3c_final(float* __restrict__ out) {
    const int b    = blockIdx.x;
    const int tid  = threadIdx.x;
    const int lane = tid & 31;
    const int wid  = tid >> 5;

    __shared__ unsigned s_sup[TOPK * WORDS];
    __shared__ float s_x1[TOPK], s_y1[TOPK], s_x2[TOPK], s_y2[TOPK];
    __shared__ float s_ar[TOPK], s_sc[TOPK], s_lab[TOPK];
    __shared__ unsigned s_keep[WORDS], s_act[WORDS];
    __shared__ int s_nkeep;

    if (tid < TOPK) {
        float4 bb = g_box4[b * TOPK + tid];
        s_x1[tid] = bb.x; s_y1[tid] = bb.y; s_x2[tid] = bb.z; s_y2[tid] = bb.w;
        float4 ax = g_aux[b * TOPK + tid];
        s_ar[tid] = ax.x; s_sc[tid] = ax.y; s_lab[tid] = ax.z;
    }
    if (tid < WORDS) s_act[tid] = 0;
    __syncthreads();

    // ---- suppression bitmask: triangle-only, register j-boxes (R7) ----
    {
        int g0   = wid * GPW;               // 32 warps, GTOT=2896 exact
        int gend = min(g0 + GPW, GTOT);
        int jb = 0, cum = 0;
        int len = 32;
        while (g0 >= cum + len) { cum += len; jb++; len = min(400, (jb + 1) * 32); }
        int j = jb * 32 + lane;
        bool jv = (j < TOPK);
        float jx1 = jv ? s_x1[j] : 0.f, jy1 = jv ? s_y1[j] : 0.f;
        float jx2 = jv ? s_x2[j] : 0.f, jy2 = jv ? s_y2[j] : 0.f;
        float jar = jv ? s_ar[j] : 0.f;
        for (int g = g0; g < gend; ++g) {
            int i = g - cum;
            if (i >= len) {
                cum += len; jb++; len = min(400, (jb + 1) * 32);
                i = 0;
                j = jb * 32 + lane;
                jv = (j < TOPK);
                jx1 = jv ? s_x1[j] : 0.f; jy1 = jv ? s_y1[j] : 0.f;
                jx2 = jv ? s_x2[j] : 0.f; jy2 = jv ? s_y2[j] : 0.f;
                jar = jv ? s_ar[j] : 0.f;
            }
            float bx1 = s_x1[i], by1 = s_y1[i];
            float bx2 = s_x2[i], by2 = s_y2[i];
            float bar = s_ar[i];
            bool sbit = false;
            if (jv && j > i) {
                float iw = fmaxf(__fsub_rn(fminf(jx2, bx2), fmaxf(jx1, bx1)), 0.0f);
                float ih = fmaxf(__fsub_rn(fminf(jy2, by2), fmaxf(jy1, by1)), 0.0f);
                float inter = __fmul_rn(iw, ih);
                float den = __fadd_rn(__fsub_rn(__fadd_rn(bar, jar), inter), 1e-12f);
                sbit = (__fdiv_rn(inter, den) > NMS_T);
            }
            unsigned wd = __ballot_sync(0xffffffffu, sbit);
            if (lane == 0) {
                s_sup[i * WORDS + jb] = wd;
                if (wd) atomicOr(&s_act[i >> 5], 1u << (i & 31));
            }
        }
    }
    if (tid < WORDS * 32) {
        bool v = (tid < TOPK) && (s_sc[tid] > CONF_T);
        unsigned mk = __ballot_sync(0xffffffffu, v);
        if (lane == 0) s_keep[wid] = mk;
    }
    __syncthreads();

    // ---- greedy: warp 0, lane w owns word w ----
    if (wid == 0) {
        unsigned kp = (lane < WORDS) ? s_keep[lane] : 0u;
        unsigned rm = (lane < WORDS) ? (kp & s_act[lane]) : 0u;
        for (;;) {
            int cnd = rm ? (lane * 32 + __ffs(rm) - 1) : 0x7FFFFFFF;
            int i = (int)__reduce_min_sync(0xffffffffu, (unsigned)cnd);
            if (i == 0x7FFFFFFF) break;
            if (lane == (i >> 5)) rm &= ~(1u << (i & 31));
            unsigned s = (lane < WORDS && lane >= (i >> 5))
                         ? s_sup[i * WORDS + lane] : 0u;
            kp &= ~s; rm &= ~s;
        }
        if (lane < WORDS) s_keep[lane] = kp;
        int nk = __popc(kp);
        #pragma unroll
        for (int d = 16; d; d >>= 1) nk += __shfl_xor_sync(0xffffffffu, nk, d);
        if (lane == 0) s_nkeep = nk;
    }
    __syncthreads();

    // ---- rank + emit ----
    {
        float* ob = out + (size_t)b * (KEEPK * 6);
        const int nkeep = s_nkeep;
        const int nk = min(nkeep, KEEPK);
        if (tid >= nk && tid < KEEPK) {
            #pragma unroll
            for (int q = 0; q < 6; q++) ob[tid * 6 + q] = 0.0f;
        }
        if (tid < TOPK) {
            bool kept = (s_keep[tid >> 5] >> (tid & 31)) & 1u;
            if (kept) {
                float sc = s_sc[tid];
                int p = 0;
                int wi = tid >> 5;
                for (int w = 0; w < wi; w++) p += __popc(s_keep[w]);
                p += __popc(s_keep[wi] & ((1u << (tid & 31)) - 1u));
                int sct = 0;
                for (int j = tid - 1; j >= 0 && s_sc[j] == sc; --j)
                    if ((s_keep[j >> 5] >> (j & 31)) & 1u) sct++;
                int ect = 0;
                for (int j = tid + 1; j < TOPK && s_sc[j] == sc; ++j)
                    if ((s_keep[j >> 5] >> (j & 31)) & 1u) ect++;
                int r = (nkeep - (p + ect + 1)) + sct;
                if (r < KEEPK) {
                    ob[r * 6 + 0] = s_lab[tid];
                    ob[r * 6 + 1] = sc;
                    ob[r * 6 + 2] = s_x1[tid];
                    ob[r * 6 + 3] = s_y1[tid];
                    ob[r * 6 + 4] = s_x2[tid];
                    ob[r * 6 + 5] = s_y2[tid];
                }
            }
        }
    }
}

extern "C" void kernel_launch(void* const* d_in, const int* in_sizes, int n_in,
                              void* d_out, int out_size) {
    const float* pred   = (const float*)d_in[0];
    const float* priors = (const float*)d_in[1];
    int nb = in_sizes[0] / (NPRI * 6);
    if (nb <= 0 || nb > NB) nb = NB;
    k1_score<<<nb * SEGS, 256>>>(pred);
    k2g_gather<<<nb * SEGS, 512>>>();
    k2s_sort<<<nb, 512>>>(pred, priors);
    k3c_final<<<nb, 1024>>>((float*)d_out);
}

// round 17
// speedup vs baseline: 1.2433x; 1.0031x over previous
#include <cuda_runtime.h>
#include <cstdint>

#define NB    128
#define NPRI  32768
#define TOPK  400
#define KEEPK 200
#define WORDS 13
#define CONF_T 0.5f
#define NMS_T  0.5f
#define BIGNEG -1000000000.0f
#define HBINS 512
#define HBASE 12224u          // order_f(0.5) >> 18
#define SEGS  16
#define SEGBOX (NPRI / SEGS)

__device__ unsigned           g_score[NB * NPRI];
__device__ unsigned long long g_cand[NB * NPRI];   // per-(image,segment) regions
__device__ unsigned           g_hist[NB * HBINS];
__device__ int                g_scnt[NB * SEGS];
__device__ float4             g_box4[NB * TOPK];   // x1,y1,x2,y2
__device__ float4             g_aux[NB * TOPK];    // area, score, label, 0
__device__ unsigned           g_sup[NB * TOPK * WORDS];

__device__ __forceinline__ unsigned order_f(float f) {
    unsigned u = __float_as_uint(f);
    return (u & 0x80000000u) ? ~u : (u | 0x80000000u);
}
__device__ __forceinline__ float unorder_f(unsigned u) {
    unsigned v = (u & 0x80000000u) ? (u ^ 0x80000000u) : ~u;
    return __uint_as_float(v);
}

// ============ K1: stream pred, emit ordered scores + 512-bin histogram ======
__global__ __launch_bounds__(256)
void k1_score(const float* __restrict__ pred) {
    const int b   = blockIdx.x >> 4;
    const int seg = blockIdx.x & 15;
    __shared__ unsigned sh[HBINS];
    sh[threadIdx.x] = 0; sh[threadIdx.x + 256] = 0;
    __syncthreads();

    const float4* P4 = reinterpret_cast<const float4*>(
        pred + (size_t)b * NPRI * 6 + (size_t)seg * SEGBOX * 6);
    uint2* S2 = reinterpret_cast<uint2*>(g_score + (size_t)b * NPRI + seg * SEGBOX);

    #pragma unroll
    for (int it = 0; it < 4; it++) {
        int e = it * 256 + threadIdx.x;
        float4 a1 = P4[3 * e + 1];
        float4 a2 = P4[3 * e + 2];
        float s0 = fmaxf(a1.x, a1.y);
        float s1 = fmaxf(a2.z, a2.w);
        unsigned u0 = order_f((s0 > CONF_T) ? s0 : BIGNEG);
        unsigned u1 = order_f((s1 > CONF_T) ? s1 : BIGNEG);
        S2[e] = make_uint2(u0, u1);
        if (s0 > CONF_T) atomicAdd(&sh[min(511u, (u0 >> 18) - HBASE)], 1u);
        if (s1 > CONF_T) atomicAdd(&sh[min(511u, (u1 >> 18) - HBASE)], 1u);
    }
    __syncthreads();
    #pragma unroll
    for (int i = threadIdx.x; i < HBINS; i += 256) {
        unsigned v = sh[i];
        if (v) atomicAdd(&g_hist[b * HBINS + i], v);
    }
}

// ===== K2g: per-block threshold recompute + gather into segment regions =====
__global__ __launch_bounds__(512)
void k2g_gather() {
    const int b   = blockIdx.x >> 4;
    const int seg = blockIdx.x & 15;
    const int tid = threadIdx.x;

    __shared__ unsigned s_ss[HBINS];
    __shared__ int s_v, s_cnt;

    s_ss[tid] = g_hist[b * HBINS + tid];
    if (tid == 0) { s_v = 0; s_cnt = 0; }
    __syncthreads();
    for (int d = 1; d < HBINS; d <<= 1) {
        unsigned v = (tid + d < HBINS) ? s_ss[tid + d] : 0u;
        __syncthreads();
        s_ss[tid] += v;
        __syncthreads();
    }
    {
        bool hit = (s_ss[tid] >= TOPK) && (tid == HBINS - 1 || s_ss[tid + 1] < TOPK);
        if (hit) s_v = tid;
    }
    __syncthreads();
    const unsigned thr = (HBASE + (unsigned)s_v) << 18;

    const uint4* S4 = reinterpret_cast<const uint4*>(
        g_score + (size_t)b * NPRI + seg * SEGBOX);
    unsigned long long* my = g_cand + (size_t)b * NPRI + (size_t)seg * SEGBOX;
    const unsigned segbase = (unsigned)(seg * SEGBOX);

    uint4 v = S4[tid];
    unsigned base_i = segbase + (unsigned)tid * 4u;
    #pragma unroll
    for (int q = 0; q < 4; q++) {
        unsigned u = (q == 0) ? v.x : (q == 1) ? v.y : (q == 2) ? v.z : v.w;
        if (u >= thr) {
            int pos = atomicAdd(&s_cnt, 1);
            my[pos] = ((unsigned long long)u << 32) |
                      (0xFFFFFFFFu - (base_i + (unsigned)q));
        }
    }
    __syncthreads();
    if (tid == 0) g_scnt[b * SEGS + seg] = s_cnt;
}

// ============ K2s: merge segments + sort + decode -> box records ============
__global__ __launch_bounds__(512)
void k2s_sort(const float* __restrict__ pred,
              const float* __restrict__ priors) {
    const int b   = blockIdx.x;
    const int tid = threadIdx.x;
    const float* P = pred + (size_t)b * NPRI * 6;
    const unsigned long long* cand = g_cand + (size_t)b * NPRI;

    __shared__ unsigned long long s_top[512];
    __shared__ unsigned s_h[256];
    __shared__ int s_pre[SEGS + 1];
    __shared__ int s_n, s_krem;
    __shared__ unsigned long long s_pv;

    g_hist[b * HBINS + tid] = 0;            // reset for next graph replay

    if (tid == 0) {
        int acc = 0;
        #pragma unroll
        for (int s = 0; s < SEGS; s++) {
            s_pre[s] = acc;
            acc += g_scnt[b * SEGS + s];
        }
        s_pre[SEGS] = acc;
    }
    __syncthreads();
    const int cnt = s_pre[SEGS];

    if (cnt <= 512) {
        unsigned long long key = 0ull;
        if (tid < cnt) {
            int s = 0;
            #pragma unroll
            for (int q = 1; q < SEGS; q++) if (tid >= s_pre[q]) s = q;
            key = cand[(size_t)s * SEGBOX + (tid - s_pre[s])];
        }
        s_top[tid] = key;
        __syncthreads();
    } else {
        if (tid == 0) { s_pv = 0ull; s_krem = TOPK; }
        __syncthreads();
        for (int byt = 7; byt >= 0; --byt) {
            if (tid < 256) s_h[tid] = 0;
            __syncthreads();
            unsigned long long pv = s_pv;
            unsigned long long hb =
                (byt == 7) ? 0ull : (0xFFFFFFFFFFFFFFFFull << ((byt + 1) * 8));
            for (int s = 0; s < SEGS; s++) {
                int c = s_pre[s + 1] - s_pre[s];
                for (int i = tid; i < c; i += 512) {
                    unsigned long long e = cand[(size_t)s * SEGBOX + i];
                    if (((e ^ pv) & hb) == 0)
                        atomicAdd(&s_h[(unsigned)((e >> (byt * 8)) & 255)], 1u);
                }
            }
            __syncthreads();
            if (tid == 0) {
                unsigned acc = 0; int d = 255;
                for (; d >= 0; --d) {
                    if (acc + s_h[d] >= (unsigned)s_krem) break;
                    acc += s_h[d];
                }
                s_krem -= (int)acc;
                s_pv |= ((unsigned long long)(unsigned)d) << (byt * 8);
            }
            __syncthreads();
        }
        unsigned long long kth = s_pv;
        if (tid == 0) s_n = 0;
        __syncthreads();
        for (int s = 0; s < SEGS; s++) {
            int c = s_pre[s + 1] - s_pre[s];
            for (int i = tid; i < c; i += 512) {
                unsigned long long e = cand[(size_t)s * SEGBOX + i];
                if (e >= kth) {
                    int p = atomicAdd(&s_n, 1);
                    if (p < 512) s_top[p] = e;
                }
            }
        }
        __syncthreads();
        int n = s_n;
        if (tid >= n) s_top[tid] = 0ull;
        __syncthreads();
    }

    for (int ksz = 2; ksz <= 512; ksz <<= 1)
        for (int j = ksz >> 1; j > 0; j >>= 1) {
            int ixj = tid ^ j;
            if (ixj > tid) {
                unsigned long long a = s_top[tid], c = s_top[ixj];
                bool sw = ((tid & ksz) == 0) ? (a < c) : (a > c);
                if (sw) { s_top[tid] = c; s_top[ixj] = a; }
            }
            __syncthreads();
        }

    if (tid < TOPK) {
        unsigned long long key = s_top[tid];
        unsigned u = (unsigned)(key >> 32);
        float sc = unorder_f(u);
        unsigned idxu = 0xFFFFFFFFu - (unsigned)(key & 0xFFFFFFFFull);
        int idx = (int)min(idxu, (unsigned)(NPRI - 1));
        const float* pp = P + 6 * idx;
        float l0 = pp[0], l1 = pp[1], l2 = pp[2], l3 = pp[3];
        float c0 = pp[4], c1 = pp[5];
        float4 pr = *reinterpret_cast<const float4*>(priors + 4 * idx);
        float cx = __fadd_rn(pr.x, __fmul_rn(__fmul_rn(l0, 0.1f), pr.z));
        float cy = __fadd_rn(pr.y, __fmul_rn(__fmul_rn(l1, 0.1f), pr.w));
        float w  = __fmul_rn(pr.z, expf(__fmul_rn(l2, 0.2f)));
        float h  = __fmul_rn(pr.w, expf(__fmul_rn(l3, 0.2f)));
        float x1 = __fsub_rn(cx, __fmul_rn(w, 0.5f));
        float y1 = __fsub_rn(cy, __fmul_rn(h, 0.5f));
        float x2 = __fadd_rn(cx, __fmul_rn(w, 0.5f));
        float y2 = __fadd_rn(cy, __fmul_rn(h, 0.5f));
        float ar = __fmul_rn(__fsub_rn(x2, x1), __fsub_rn(y2, y1));
        g_box4[b * TOPK + tid] = make_float4(x1, y1, x2, y2);
        g_aux[b * TOPK + tid]  = make_float4(ar, sc, (c1 > c0) ? 1.0f : 0.0f, 0.0f);
    }
}

// ===== K3b: suppression masks, float4 boxes, one j-column per block =========
__global__ __launch_bounds__(512)
void k3b_mask() {
    const int jb = blockIdx.x;            // 0..12
    const int b  = blockIdx.y;
    const int lane = threadIdx.x & 31;
    const int wrp  = threadIdx.x >> 5;    // 0..15

    __shared__ float4 s_box[TOPK];
    __shared__ float  s_ar[TOPK];
    if (threadIdx.x < TOPK) {
        s_box[threadIdx.x] = g_box4[b * TOPK + threadIdx.x];
        s_ar[threadIdx.x]  = g_aux[b * TOPK + threadIdx.x].x;
    }
    __syncthreads();

    int j = jb * 32 + lane;
    bool jv = (j < TOPK);
    float4 jb4 = jv ? s_box[j] : make_float4(0.f, 0.f, 0.f, 0.f);
    float  jar = jv ? s_ar[j]  : 0.f;

    const int rows = min(TOPK, (jb + 1) * 32);
    unsigned* outw = g_sup + ((size_t)b * TOPK) * WORDS + jb;
    for (int i = wrp; i < rows; i += 16) {
        float4 bb = s_box[i];
        float bar = s_ar[i];
        bool sbit = false;
        if (jv && j > i) {
            float iw = fmaxf(__fsub_rn(fminf(jb4.z, bb.z), fmaxf(jb4.x, bb.x)), 0.0f);
            float ih = fmaxf(__fsub_rn(fminf(jb4.w, bb.w), fmaxf(jb4.y, bb.y)), 0.0f);
            float inter = __fmul_rn(iw, ih);
            float den = __fadd_rn(__fsub_rn(__fadd_rn(bar, jar), inter), 1e-12f);
            sbit = (__fdiv_rn(inter, den) > NMS_T);
        }
        unsigned wd = __ballot_sync(0xffffffffu, sbit);
        if (lane == 0) outw[i * WORDS] = wd;
    }
}

// ============ K3c: greedy NMS + rank + emit =================================
__global__ __launch_bounds__(1024)
void k3c_final(float* __restrict__ out) {
    const int b    = blockIdx.x;
    const int tid  = threadIdx.x;
    const int lane = tid & 31;
    const int wid  = tid >> 5;

    __shared__ unsigned s_sup[TOPK * WORDS];
    __shared__ float4 s_box[TOPK];
    __shared__ float s_sc[TOPK], s_lab[TOPK];
    __shared__ unsigned s_keep[WORDS], s_act[WORDS];
    __shared__ int s_nkeep;

    const unsigned* supg = g_sup + ((size_t)b * TOPK) * WORDS;
    for (int i = tid; i < TOPK * WORDS; i += 1024) s_sup[i] = supg[i];
    if (tid < TOPK) {
        s_box[tid] = g_box4[b * TOPK + tid];
        float4 ax = g_aux[b * TOPK + tid];
        s_sc[tid] = ax.y; s_lab[tid] = ax.z;
    }
    __syncthreads();

    if (tid < WORDS * 32) {
        bool a = false;
        if (tid < TOPK) {
            unsigned o = 0;
            for (int w = tid >> 5; w < WORDS; w++) o |= s_sup[tid * WORDS + w];
            a = (o != 0);
        }
        unsigned ma = __ballot_sync(0xffffffffu, a);
        bool v = (tid < TOPK) && (s_sc[tid] > CONF_T);
        unsigned mk = __ballot_sync(0xffffffffu, v);
        if (lane == 0) { s_act[wid] = ma; s_keep[wid] = mk; }
    }
    __syncthreads();

    // greedy: warp 0, lane w owns word w
    if (wid == 0) {
        unsigned kp = (lane < WORDS) ? s_keep[lane] : 0u;
        unsigned rm = (lane < WORDS) ? (kp & s_act[lane]) : 0u;
        for (;;) {
            int cnd = rm ? (lane * 32 + __ffs(rm) - 1) : 0x7FFFFFFF;
            int i = (int)__reduce_min_sync(0xffffffffu, (unsigned)cnd);
            if (i == 0x7FFFFFFF) break;
            if (lane == (i >> 5)) rm &= ~(1u << (i & 31));
            unsigned s = (lane < WORDS && lane >= (i >> 5))
                         ? s_sup[i * WORDS + lane] : 0u;
            kp &= ~s; rm &= ~s;
        }
        if (lane < WORDS) s_keep[lane] = kp;
        int nk = __popc(kp);
        #pragma unroll
        for (int d = 16; d; d >>= 1) nk += __shfl_xor_sync(0xffffffffu, nk, d);
        if (lane == 0) s_nkeep = nk;
    }
    __syncthreads();

    // rank + emit
    {
        float* ob = out + (size_t)b * (KEEPK * 6);
        const int nkeep = s_nkeep;
        const int nk = min(nkeep, KEEPK);
        if (tid >= nk && tid < KEEPK) {
            #pragma unroll
            for (int q = 0; q < 6; q++) ob[tid * 6 + q] = 0.0f;
        }
        if (tid < TOPK) {
            bool kept = (s_keep[tid >> 5] >> (tid & 31)) & 1u;
            if (kept) {
                float sc = s_sc[tid];
                int p = 0;
                int wi = tid >> 5;
                for (int w = 0; w < wi; w++) p += __popc(s_keep[w]);
                p += __popc(s_keep[wi] & ((1u << (tid & 31)) - 1u));
                int sct = 0;
                for (int j = tid - 1; j >= 0 && s_sc[j] == sc; --j)
                    if ((s_keep[j >> 5] >> (j & 31)) & 1u) sct++;
                int ect = 0;
                for (int j = tid + 1; j < TOPK && s_sc[j] == sc; ++j)
                    if ((s_keep[j >> 5] >> (j & 31)) & 1u) ect++;
                int r = (nkeep - (p + ect + 1)) + sct;
                if (r < KEEPK) {
                    float4 bb = s_box[tid];
                    ob[r * 6 + 0] = s_lab[tid];
                    ob[r * 6 + 1] = sc;
                    ob[r * 6 + 2] = bb.x;
                    ob[r * 6 + 3] = bb.y;
                    ob[r * 6 + 4] = bb.z;
                    ob[r * 6 + 5] = bb.w;
                }
            }
        }
    }
}

extern "C" void kernel_launch(void* const* d_in, const int* in_sizes, int n_in,
                              void* d_out, int out_size) {
    const float* pred   = (const float*)d_in[0];
    const float* priors = (const float*)d_in[1];
    int nb = in_sizes[0] / (NPRI * 6);
    if (nb <= 0 || nb > NB) nb = NB;
    k1_score<<<nb * SEGS, 256>>>(pred);
    k2g_gather<<<nb * SEGS, 512>>>();
    k2s_sort<<<nb, 512>>>(pred, priors);
    k3b_mask<<<dim3(WORDS, nb), 512>>>();
    k3c_final<<<nb, 1024>>>((float*)d_out);
}